// round 2
// baseline (speedup 1.0000x reference)
#include <cuda_runtime.h>

#define T_DIM 2048
#define R_DIM 256
#define BS_DIM 32            // B*S
#define PPB 4                // problems (r values) per block
#define NCOLS 8              // PPB * 2 (x and y)
#define CSTRIDE 2049         // padded column stride in smem floats

__device__ unsigned int g_min_bits;

__global__ void init_kernel(float* out) {
    if (threadIdx.x == 0) g_min_bits = 0xFFFFFFFFu;
    if (threadIdx.x < 4) out[threadIdx.x] = 0.0f;
}

__device__ __forceinline__ unsigned int float_to_key(float f) {
    unsigned int b = __float_as_uint(f);
    return (b & 0x80000000u) ? ~b : (b | 0x80000000u);
}

__global__ void __launch_bounds__(256) min_kernel(const float4* __restrict__ x,
                                                  const float4* __restrict__ y, int n4) {
    int stride = gridDim.x * blockDim.x;
    float m = 3.4e38f;
    for (int i = blockIdx.x * blockDim.x + threadIdx.x; i < n4; i += stride) {
        float4 a = x[i];
        float4 b = y[i];
        m = fminf(m, fminf(fminf(a.x, a.y), fminf(a.z, a.w)));
        m = fminf(m, fminf(fminf(b.x, b.y), fminf(b.z, b.w)));
    }
    for (int o = 16; o; o >>= 1) m = fminf(m, __shfl_xor_sync(0xffffffffu, m, o));
    __shared__ float wmin[8];
    int lid = threadIdx.x & 31, wid = threadIdx.x >> 5;
    if (lid == 0) wmin[wid] = m;
    __syncthreads();
    if (wid == 0) {
        m = (lid < 8) ? wmin[lid] : 3.4e38f;
        for (int o = 16; o; o >>= 1) m = fminf(m, __shfl_xor_sync(0xffffffffu, m, o));
        if (lid == 0) atomicMin(&g_min_bits, float_to_key(m));
    }
}

// One block handles PPB=4 consecutive r-problems for one (b,s).
// smem columns 0..3: x cdfs, 4..7: y cdfs.
__global__ void __launch_bounds__(256) w2_kernel(const float* __restrict__ x,
                                                 const float* __restrict__ y,
                                                 float* __restrict__ out) {
    extern __shared__ float sm[];  // NCOLS * CSTRIDE floats
    __shared__ float segsum[NCOLS][33];
    __shared__ float warr[8];

    const int tid = threadIdx.x;
    const int bs = blockIdx.x >> 6;          // 0..31
    const int r0 = (blockIdx.x & 63) * PPB;  // 0..252

    // decode global min
    unsigned int k = g_min_bits;
    float mn = (k & 0x80000000u) ? __uint_as_float(k & 0x7FFFFFFFu)
                                 : __uint_as_float(~k);
    float shift = (mn < 0.0f) ? (-1.1f * mn) : 0.0f;  // value used: v + shift

    // ---- load: 4 consecutive r per t as float4, scatter into smem columns ----
    {
        const float* srcs[2] = {x, y};
        #pragma unroll
        for (int a = 0; a < 2; a++) {
            const float* src = srcs[a] + (size_t)bs * T_DIM * R_DIM + r0;
            float* dst = sm + a * PPB * CSTRIDE;
            #pragma unroll
            for (int it = 0; it < 8; it++) {
                int t = it * 256 + tid;
                float4 v = *(const float4*)(src + (size_t)t * R_DIM);
                dst[0 * CSTRIDE + t] = v.x + shift;
                dst[1 * CSTRIDE + t] = v.y + shift;
                dst[2 * CSTRIDE + t] = v.z + shift;
                dst[3 * CSTRIDE + t] = v.w + shift;
            }
        }
    }
    __syncthreads();

    // ---- in-smem cumsum per column: 32 segments of 64, per column 32 threads ----
    {
        int col = tid & 7;       // 0..7
        int seg = tid >> 3;      // 0..31
        float* c = sm + col * CSTRIDE + seg * 64;
        float run = 0.0f;
        #pragma unroll 8
        for (int i = 0; i < 64; i++) { run += c[i]; c[i] = run; }
        segsum[col][seg] = run;
        __syncthreads();
        float off = 0.0f, tot = 0.0f;
        #pragma unroll
        for (int j = 0; j < 32; j++) {
            float s = segsum[col][j];
            if (j < seg) off += s;
            tot += s;
        }
        float inv = 1.0f / tot;
        #pragma unroll 8
        for (int i = 0; i < 64; i++) c[i] = (c[i] + off) * inv;
    }
    __syncthreads();

    // ---- search phase: each thread handles 64 endpoints of one side of one problem ----
    const int p = tid >> 6;          // problem 0..3
    const int sub = tid & 63;
    const int side = sub >> 5;       // 0: endpoints from x-cdf, 1: from y-cdf
    const int lane32 = sub & 31;
    const float* cx = sm + p * CSTRIDE;
    const float* cy = sm + (PPB + p) * CSTRIDE;
    const float* A  = side ? cy : cx;   // endpoint array
    const float* Bp = side ? cx : cy;   // searched array

    const int i0 = lane32 * 64;
    float q0 = A[i0];
    // lower_bound(Bp, q0): j = #elements < q0
    int j = 0;
    #pragma unroll
    for (int stepv = 1024; stepv > 0; stepv >>= 1) {
        int nj = j + stepv;
        if (nj <= 2048 && Bp[nj - 1] < q0) j = nj;
    }
    float pbv = (j > 0) ? Bp[j - 1] : 0.0f;   // largest B value < current q
    float prevA = (i0 > 0) ? A[i0 - 1] : 0.0f;

    float acc = 0.0f;
    const float invn = 1.0f / 2048.0f;
    for (int ii = 0; ii < 64; ii++) {
        int i = i0 + ii;
        float q = A[i];
        while (j < 2048) {
            float b = Bp[j];
            if (b < q) { pbv = b; j++; }
            else break;
        }
        float prev = fmaxf(prevA, pbv);
        float d = q - prev;
        int jc = (j < 2047) ? j : 2047;
        float diff = (float)(i - jc) * invn;
        acc += d * diff * diff;
        prevA = q;
    }

    // ---- reduce: warps 2p, 2p+1 belong to problem p; all → out[b] ----
    for (int o = 16; o; o >>= 1) acc += __shfl_xor_sync(0xffffffffu, acc, o);
    int wid = tid >> 5;
    if ((tid & 31) == 0) warr[wid] = acc;
    __syncthreads();
    if (tid < 4) {
        float s = warr[2 * tid] + warr[2 * tid + 1];
        atomicAdd(&out[bs >> 3], s);   // b = (bs*256+r) >> 11 = bs >> 3
    }
}

extern "C" void kernel_launch(void* const* d_in, const int* in_sizes, int n_in,
                              void* d_out, int out_size) {
    const float* x = (const float*)d_in[0];
    const float* y = (const float*)d_in[1];
    float* out = (float*)d_out;

    init_kernel<<<1, 32>>>(out);
    min_kernel<<<2048, 256>>>((const float4*)x, (const float4*)y,
                              (BS_DIM * T_DIM * R_DIM) / 4);

    static bool attr_set = false;
    if (!attr_set) {
        cudaFuncSetAttribute(w2_kernel, cudaFuncAttributeMaxDynamicSharedMemorySize,
                             NCOLS * CSTRIDE * sizeof(float));
        attr_set = true;
    }
    w2_kernel<<<BS_DIM * (R_DIM / PPB), 256, NCOLS * CSTRIDE * sizeof(float)>>>(x, y, out);
}

// round 4
// speedup vs baseline: 2.5964x; 2.5964x over previous
#include <cuda_runtime.h>

#define T_DIM 2048
#define R_DIM 256
#define BS_DIM 32
#define IDX(t) ((t) + ((t) >> 5))   // smem skew: 1 pad float per 32
#define CSK 2112                    // skewed column size: 2048 + 64

// 128 MB transposed CDF scratch: [array][bs][r][t]
__device__ float g_cdf[2][BS_DIM][R_DIM][T_DIM];
// per-segment totals (segments of 256 t): [array][bs][r][seg]
__device__ float g_segtot[2][BS_DIM][R_DIM][8];
__device__ unsigned int g_min_bits;

__global__ void init_kernel(float* out) {
    if (threadIdx.x == 0) g_min_bits = 0xFFFFFFFFu;
    if (threadIdx.x < 4) out[threadIdx.x] = 0.0f;
}

__device__ __forceinline__ unsigned int float_to_key(float f) {
    unsigned int b = __float_as_uint(f);
    return (b & 0x80000000u) ? ~b : (b | 0x80000000u);
}

// ---------------- Kernel A: transpose + segment cumsum + global min ----------------
// grid 512: [array(2)][bs(32)][rtile(8)], 256 threads. Warp w = t-segment w (256 t).
__global__ void __launch_bounds__(256) cdf_kernel(const float* __restrict__ x,
                                                  const float* __restrict__ y) {
    __shared__ float tile[8][32][33];
    __shared__ float wmin[8];

    const int bid = blockIdx.x;
    const int a   = bid >> 8;
    const int rem = bid & 255;
    const int bs  = rem >> 3;
    const int r0  = (rem & 7) * 32;

    const int lane = threadIdx.x & 31;   // r'
    const int seg  = threadIdx.x >> 5;   // t-segment / warp id

    const float* src = (a ? y : x) + (size_t)bs * T_DIM * R_DIM + r0 + lane;

    float run = 0.0f;
    float mn = 3.4e38f;

    const int row = lane >> 3;   // 0..3
    const int c4  = lane & 7;    // 0..7

    #pragma unroll 1
    for (int ch = 0; ch < 8; ch++) {
        const int t0 = seg * 256 + ch * 32;
        float v[32];
        #pragma unroll
        for (int i = 0; i < 32; i++) v[i] = src[(size_t)(t0 + i) * R_DIM];
        #pragma unroll
        for (int i = 0; i < 32; i++) {
            mn = fminf(mn, v[i]);
            run += v[i];
            tile[seg][lane][i] = run;
        }
        __syncwarp();
        // drain transposed: scalar LDS (conflict-free with pad 33), STG.128
        #pragma unroll
        for (int rb = 0; rb < 8; rb++) {
            int rr = rb * 4 + row;
            float4 o;
            o.x = tile[seg][rr][c4 * 4 + 0];
            o.y = tile[seg][rr][c4 * 4 + 1];
            o.z = tile[seg][rr][c4 * 4 + 2];
            o.w = tile[seg][rr][c4 * 4 + 3];
            // build in registers, single 16B global store (t0+c4*4 is 16B aligned)
            float* gp = &g_cdf[a][bs][r0 + rr][t0 + c4 * 4];
            gp[0] = o.x; gp[1] = o.y; gp[2] = o.z; gp[3] = o.w;
        }
        __syncwarp();
    }
    g_segtot[a][bs][r0 + lane][seg] = run;

    // block min reduce -> atomicMin
    for (int o = 16; o; o >>= 1) mn = fminf(mn, __shfl_xor_sync(0xffffffffu, mn, o));
    if (lane == 0) wmin[seg] = mn;
    __syncthreads();
    if (threadIdx.x == 0) {
        float m = wmin[0];
        #pragma unroll
        for (int i = 1; i < 8; i++) m = fminf(m, wmin[i]);
        atomicMin(&g_min_bits, float_to_key(m));
    }
}

// ---------------- Kernel B: stage normalized CDFs in skewed smem + W2 merge ----------------
// grid 4096: [bs(32)][rpair(128)], 256 threads, 2 problems per block.
__global__ void __launch_bounds__(256) w2_kernel(float* __restrict__ out) {
    __shared__ float sm[4 * CSK];
    __shared__ float coff[4][8];
    __shared__ float cinv[4];
    __shared__ float warr[8];

    const int tid = threadIdx.x;
    const int bs  = blockIdx.x >> 7;
    const int r0  = (blockIdx.x & 127) * 2;

    // decode global min -> shift
    unsigned int k = g_min_bits;
    float mnv = (k & 0x80000000u) ? __uint_as_float(k & 0x7FFFFFFFu)
                                  : __uint_as_float(~k);
    const float shift = (mnv < 0.0f) ? (-1.1f * mnv) : 0.0f;

    // per-column segment-offset prefix + normalization
    if (tid < 4) {
        int c = tid, aa = c & 1, pp = c >> 1;
        const float* st = g_segtot[aa][bs][r0 + pp];
        float runp = 0.0f;
        #pragma unroll
        for (int s = 0; s < 8; s++) { coff[c][s] = runp; runp += st[s]; }
        cinv[c] = 1.0f / (runp + 2048.0f * shift);
    }
    __syncthreads();

    // stage: coalesced float4 global loads, transform, scalar skewed smem stores
    {
        const int c = tid >> 6;
        const int l64 = tid & 63;
        const int aa = c & 1, pp = c >> 1;
        const float4* srcc = (const float4*)&g_cdf[aa][bs][r0 + pp][0];
        float* dst = sm + c * CSK;
        const float inv = cinv[c];
        #pragma unroll
        for (int it = 0; it < 8; it++) {
            int t4 = it * 64 + l64;
            float4 v = srcc[t4];
            int t = t4 * 4;
            float off = coff[c][t >> 8];
            dst[IDX(t + 0)] = (v.x + off + (float)(t + 1) * shift) * inv;
            dst[IDX(t + 1)] = (v.y + off + (float)(t + 2) * shift) * inv;
            dst[IDX(t + 2)] = (v.z + off + (float)(t + 3) * shift) * inv;
            dst[IDX(t + 3)] = (v.w + off + (float)(t + 4) * shift) * inv;
        }
    }
    __syncthreads();

    // search/merge: 64 threads per (problem, side), 32 endpoints each
    const int p   = tid >> 7;
    const int sub = tid & 127;
    const int side = sub >> 6;
    const int l   = sub & 63;
    const float* A  = sm + (p * 2 + side) * CSK;
    const float* Bp = sm + (p * 2 + (side ^ 1)) * CSK;

    const int i0 = l * 32;
    float q0 = A[IDX(i0)];
    int j = 0;
    #pragma unroll
    for (int st = 1024; st; st >>= 1) {
        int nj = j + st;
        if (nj <= 2048 && Bp[IDX(nj - 1)] < q0) j = nj;
    }
    float pbv   = j  ? Bp[IDX(j - 1)]  : 0.0f;
    float prevA = i0 ? A[IDX(i0 - 1)] : 0.0f;

    float acc = 0.0f;
    const float invn = 1.0f / 2048.0f;
    #pragma unroll 4
    for (int ii = 0; ii < 32; ii++) {
        int i = i0 + ii;
        float q = A[IDX(i)];
        while (j < 2048) {
            float b = Bp[IDX(j)];
            if (b < q) { pbv = b; j++; }
            else break;
        }
        float prev = fmaxf(prevA, pbv);
        float d = q - prev;
        int jc = (j < 2047) ? j : 2047;
        float diff = (float)(i - jc) * invn;
        acc += d * diff * diff;
        prevA = q;
    }

    // block reduce -> single atomicAdd into out[b]
    for (int o = 16; o; o >>= 1) acc += __shfl_xor_sync(0xffffffffu, acc, o);
    const int wid = tid >> 5;
    if ((tid & 31) == 0) warr[wid] = acc;
    __syncthreads();
    if (tid == 0) {
        float s = 0.0f;
        #pragma unroll
        for (int i = 0; i < 8; i++) s += warr[i];
        atomicAdd(&out[bs >> 3], s);
    }
}

extern "C" void kernel_launch(void* const* d_in, const int* in_sizes, int n_in,
                              void* d_out, int out_size) {
    const float* x = (const float*)d_in[0];
    const float* y = (const float*)d_in[1];
    float* out = (float*)d_out;

    init_kernel<<<1, 32>>>(out);
    cdf_kernel<<<2 * BS_DIM * 8, 256>>>(x, y);
    w2_kernel<<<BS_DIM * (R_DIM / 2), 256>>>(out);
}

// round 5
// speedup vs baseline: 2.8108x; 1.0826x over previous
#include <cuda_runtime.h>
#include <cfloat>

#define T_DIM 2048
#define R_DIM 256
#define BS_DIM 32
#define IDX(t) ((t) + ((t) >> 5))   // smem skew: 1 pad float per 32
#define CSK 2112                    // skewed column size: 2048 + 64

// 128 MB transposed CDF scratch: [array][bs][r][t]
__device__ float g_cdf[2][BS_DIM][R_DIM][T_DIM];
// per-segment totals (segments of 256 t): [array][bs][r][seg]
__device__ float g_segtot[2][BS_DIM][R_DIM][8];
// per-block minima from cdf_kernel (512 blocks)
__device__ float g_blockmin[512];

// ---------------- Kernel A: transpose + segment cumsum + per-block min ----------------
// grid 512: [array(2)][bs(32)][rtile(8)], 256 threads. Warp = t-segment (256 t).
__global__ void __launch_bounds__(256) cdf_kernel(const float* __restrict__ x,
                                                  const float* __restrict__ y,
                                                  float* __restrict__ out) {
    __shared__ float tile[8][32][33];
    __shared__ float wmin[8];

    const int bid = blockIdx.x;
    const int a   = bid >> 8;
    const int rem = bid & 255;
    const int bs  = rem >> 3;
    const int r0  = (rem & 7) * 32;

    if (bid == 0 && threadIdx.x < 4) out[threadIdx.x] = 0.0f;

    const int lane = threadIdx.x & 31;   // r'
    const int seg  = threadIdx.x >> 5;   // t-segment / warp id

    const float* src = (a ? y : x) + (size_t)bs * T_DIM * R_DIM + r0 + lane;

    float run = 0.0f;
    float mn = FLT_MAX;

    const int row = lane >> 3;   // 0..3
    const int c4  = lane & 7;    // 0..7

    #pragma unroll 1
    for (int ch = 0; ch < 8; ch++) {
        const int t0 = seg * 256 + ch * 32;
        float v[32];
        #pragma unroll
        for (int i = 0; i < 32; i++) v[i] = src[(size_t)(t0 + i) * R_DIM];
        #pragma unroll
        for (int i = 0; i < 32; i++) {
            mn = fminf(mn, v[i]);
            run += v[i];
            tile[seg][lane][i] = run;
        }
        __syncwarp();
        // drain transposed: scalar LDS (conflict-free with pad 33), vectorizable STG
        #pragma unroll
        for (int rb = 0; rb < 8; rb++) {
            int rr = rb * 4 + row;
            float o0 = tile[seg][rr][c4 * 4 + 0];
            float o1 = tile[seg][rr][c4 * 4 + 1];
            float o2 = tile[seg][rr][c4 * 4 + 2];
            float o3 = tile[seg][rr][c4 * 4 + 3];
            float* gp = &g_cdf[a][bs][r0 + rr][t0 + c4 * 4];
            gp[0] = o0; gp[1] = o1; gp[2] = o2; gp[3] = o3;
        }
        __syncwarp();
    }
    g_segtot[a][bs][r0 + lane][seg] = run;

    // block min reduce -> g_blockmin[bid]
    for (int o = 16; o; o >>= 1) mn = fminf(mn, __shfl_xor_sync(0xffffffffu, mn, o));
    if (lane == 0) wmin[seg] = mn;
    __syncthreads();
    if (threadIdx.x == 0) {
        float m = wmin[0];
        #pragma unroll
        for (int i = 1; i < 8; i++) m = fminf(m, wmin[i]);
        g_blockmin[bid] = m;
    }
}

// ---------------- Kernel B: stage normalized CDFs + merge-path W2 ----------------
// grid 4096: [bs(32)][rpair(128)], 256 threads, 2 problems per block.
__global__ void __launch_bounds__(256) w2_kernel(float* __restrict__ out) {
    __shared__ float sm[4 * CSK];
    __shared__ float coff[4][8];
    __shared__ float cinv[4];
    __shared__ float redsm[8];
    __shared__ float warr[8];

    const int tid = threadIdx.x;
    const int bs  = blockIdx.x >> 7;
    const int r0  = (blockIdx.x & 127) * 2;

    // ---- global min from g_blockmin (512 entries, L2-resident) ----
    {
        float m = fminf(g_blockmin[tid], g_blockmin[tid + 256]);
        for (int o = 16; o; o >>= 1) m = fminf(m, __shfl_xor_sync(0xffffffffu, m, o));
        if ((tid & 31) == 0) redsm[tid >> 5] = m;
    }
    __syncthreads();
    float mnv = redsm[0];
    #pragma unroll
    for (int i = 1; i < 8; i++) mnv = fminf(mnv, redsm[i]);
    const float shift = (mnv < 0.0f) ? (-1.1f * mnv) : 0.0f;

    // per-column segment-offset prefix + normalization
    if (tid < 4) {
        int c = tid, aa = c & 1, pp = c >> 1;
        const float* st = g_segtot[aa][bs][r0 + pp];
        float runp = 0.0f;
        #pragma unroll
        for (int s = 0; s < 8; s++) { coff[c][s] = runp; runp += st[s]; }
        cinv[c] = 1.0f / (runp + 2048.0f * shift);
    }
    __syncthreads();

    // stage: coalesced float4 global loads, transform, scalar skewed smem stores
    {
        const int c = tid >> 6;
        const int l64 = tid & 63;
        const int aa = c & 1, pp = c >> 1;
        const float4* srcc = (const float4*)&g_cdf[aa][bs][r0 + pp][0];
        float* dst = sm + c * CSK;
        const float inv = cinv[c];
        #pragma unroll
        for (int it = 0; it < 8; it++) {
            int t4 = it * 64 + l64;
            float4 v = srcc[t4];
            int t = t4 * 4;
            float off = coff[c][t >> 8];
            dst[IDX(t + 0)] = (v.x + off + (float)(t + 1) * shift) * inv;
            dst[IDX(t + 1)] = (v.y + off + (float)(t + 2) * shift) * inv;
            dst[IDX(t + 2)] = (v.z + off + (float)(t + 3) * shift) * inv;
            dst[IDX(t + 3)] = (v.w + off + (float)(t + 4) * shift) * inv;
        }
    }
    __syncthreads();

    // ---- merge-path: 128 threads per problem, 32 merged endpoints each ----
    const int p = tid >> 7;          // problem 0..1
    const int l = tid & 127;         // chunk id
    const int k0 = l * 32;           // merged rank of first element
    const float* A = sm + (p * 2 + 0) * CSK;
    const float* B = sm + (p * 2 + 1) * CSK;

    // diagonal binary search: i = #A among first k0 merged (A-first on ties)
    int lo = (k0 > T_DIM) ? (k0 - T_DIM) : 0;
    int hi = (k0 < T_DIM) ? k0 : T_DIM;
    while (lo < hi) {
        int mid = (lo + hi) >> 1;
        if (A[IDX(mid)] <= B[IDX(k0 - 1 - mid)]) lo = mid + 1;
        else hi = mid;
    }
    int i = lo;
    int j = k0 - lo;

    float prevA = i ? A[IDX(i - 1)] : 0.0f;
    float prevB = j ? B[IDX(j - 1)] : 0.0f;
    float prev = fmaxf(prevA, prevB);
    float aq = (i < T_DIM) ? A[IDX(i)] : FLT_MAX;
    float bq = (j < T_DIM) ? B[IDX(j)] : FLT_MAX;

    float acc = 0.0f;
    const float invn = 1.0f / 2048.0f;
    #pragma unroll 4
    for (int s = 0; s < 32; s++) {
        bool takeA = (aq <= bq);
        float q = takeA ? aq : bq;
        float d = q - prev;
        prev = q;
        int ic = (i < 2047) ? i : 2047;
        int jc = (j < 2047) ? j : 2047;
        float diff = (float)(ic - jc) * invn;
        acc += d * diff * diff;
        if (takeA) { i++; aq = (i < T_DIM) ? A[IDX(i)] : FLT_MAX; }
        else       { j++; bq = (j < T_DIM) ? B[IDX(j)] : FLT_MAX; }
    }

    // block reduce -> single atomicAdd into out[b]
    for (int o = 16; o; o >>= 1) acc += __shfl_xor_sync(0xffffffffu, acc, o);
    const int wid = tid >> 5;
    if ((tid & 31) == 0) warr[wid] = acc;
    __syncthreads();
    if (tid == 0) {
        float s = 0.0f;
        #pragma unroll
        for (int i2 = 0; i2 < 8; i2++) s += warr[i2];
        atomicAdd(&out[bs >> 3], s);
    }
}

extern "C" void kernel_launch(void* const* d_in, const int* in_sizes, int n_in,
                              void* d_out, int out_size) {
    const float* x = (const float*)d_in[0];
    const float* y = (const float*)d_in[1];
    float* out = (float*)d_out;

    cdf_kernel<<<2 * BS_DIM * 8, 256>>>(x, y, out);
    w2_kernel<<<BS_DIM * (R_DIM / 2), 256>>>(out);
}

// round 6
// speedup vs baseline: 2.9865x; 1.0625x over previous
#include <cuda_runtime.h>
#include <cfloat>

#define T_DIM 2048
#define R_DIM 256
#define BS_DIM 32
#define IDX(t) ((t) + ((t) >> 5))   // smem skew: 1 pad float per 32
#define CSK 2112                    // skewed column size: 2048 + 64

// 128 MB transposed CDF scratch: [array][bs][r][t]
__device__ float g_cdf[2][BS_DIM][R_DIM][T_DIM];
// per-segment totals (segments of 128 t): [array][bs][r][seg16]
__device__ float g_segtot[2][BS_DIM][R_DIM][16];
// per-block minima from cdf_kernel (1024 blocks)
__device__ float g_blockmin[1024];

// ---------------- Kernel A: transpose + segment cumsum + per-block min ----------------
// grid 1024: [array(2)][bs(32)][rtile(8)][thalf(2)], 256 threads.
// Warp = 128-t segment; lane = r within 32-wide r tile.
__global__ void __launch_bounds__(256) cdf_kernel(const float* __restrict__ x,
                                                  const float* __restrict__ y,
                                                  float* __restrict__ out) {
    __shared__ float tile[8][32][33];
    __shared__ float wmin[8];

    const int bid = blockIdx.x;
    const int a    = bid >> 9;
    const int rem  = bid & 511;
    const int bs   = rem >> 4;
    const int rem2 = rem & 15;
    const int r0   = (rem2 >> 1) * 32;
    const int tb   = (rem2 & 1) * 1024;

    if (bid == 0 && threadIdx.x < 4) out[threadIdx.x] = 0.0f;

    const int lane = threadIdx.x & 31;   // r'
    const int seg  = threadIdx.x >> 5;   // warp id -> 128-t segment

    const float* src = (a ? y : x) + (size_t)bs * T_DIM * R_DIM + r0 + lane;

    float run = 0.0f;
    float mn = FLT_MAX;

    const int row = lane >> 3;   // 0..3
    const int c4  = lane & 7;    // 0..7

    #pragma unroll 1
    for (int ch = 0; ch < 4; ch++) {
        const int t0 = tb + seg * 128 + ch * 32;
        float v[32];
        #pragma unroll
        for (int i = 0; i < 32; i++) v[i] = src[(size_t)(t0 + i) * R_DIM];
        #pragma unroll
        for (int i = 0; i < 32; i++) {
            mn = fminf(mn, v[i]);
            run += v[i];
            tile[seg][lane][i] = run;
        }
        __syncwarp();
        // drain transposed: scalar LDS (conflict-free, pad 33), contiguous 128B STG groups
        #pragma unroll
        for (int rb = 0; rb < 8; rb++) {
            int rr = rb * 4 + row;
            float o0 = tile[seg][rr][c4 * 4 + 0];
            float o1 = tile[seg][rr][c4 * 4 + 1];
            float o2 = tile[seg][rr][c4 * 4 + 2];
            float o3 = tile[seg][rr][c4 * 4 + 3];
            float* gp = &g_cdf[a][bs][r0 + rr][t0 + c4 * 4];
            gp[0] = o0; gp[1] = o1; gp[2] = o2; gp[3] = o3;
        }
        __syncwarp();
    }
    g_segtot[a][bs][r0 + lane][(tb >> 7) + seg] = run;

    // block min reduce -> g_blockmin[bid]
    for (int o = 16; o; o >>= 1) mn = fminf(mn, __shfl_xor_sync(0xffffffffu, mn, o));
    if (lane == 0) wmin[seg] = mn;
    __syncthreads();
    if (threadIdx.x == 0) {
        float m = wmin[0];
        #pragma unroll
        for (int i = 1; i < 8; i++) m = fminf(m, wmin[i]);
        g_blockmin[bid] = m;
    }
}

// ---------------- Kernel B: stage normalized CDFs + merge-path W2 ----------------
// grid 4096: [bs(32)][rpair(128)], 256 threads, 2 problems per block.
__global__ void __launch_bounds__(256) w2_kernel(float* __restrict__ out) {
    __shared__ float sm[4 * CSK + 32];   // +32 pad: final-iteration dead loads
    __shared__ float coff[4][16];
    __shared__ float cinv[4];
    __shared__ float redsm[8];
    __shared__ float warr[8];

    const int tid = threadIdx.x;
    const int bs  = blockIdx.x >> 7;
    const int r0  = (blockIdx.x & 127) * 2;

    // ---- global min from g_blockmin (1024 entries, L2-resident) ----
    {
        float m = fminf(fminf(g_blockmin[tid],       g_blockmin[tid + 256]),
                        fminf(g_blockmin[tid + 512], g_blockmin[tid + 768]));
        for (int o = 16; o; o >>= 1) m = fminf(m, __shfl_xor_sync(0xffffffffu, m, o));
        if ((tid & 31) == 0) redsm[tid >> 5] = m;
    }
    __syncthreads();
    float mnv = redsm[0];
    #pragma unroll
    for (int i = 1; i < 8; i++) mnv = fminf(mnv, redsm[i]);
    const float shift = (mnv < 0.0f) ? (-1.1f * mnv) : 0.0f;

    // per-column segment-offset prefix + normalization
    if (tid < 4) {
        int c = tid, aa = c & 1, pp = c >> 1;
        const float* st = g_segtot[aa][bs][r0 + pp];
        float runp = 0.0f;
        #pragma unroll
        for (int s = 0; s < 16; s++) { coff[c][s] = runp; runp += st[s]; }
        cinv[c] = 1.0f / (runp + 2048.0f * shift);
    }
    __syncthreads();

    // stage: coalesced float4 global loads, transform, scalar skewed smem stores
    {
        const int c = tid >> 6;
        const int l64 = tid & 63;
        const int aa = c & 1, pp = c >> 1;
        const float4* srcc = (const float4*)&g_cdf[aa][bs][r0 + pp][0];
        float* dst = sm + c * CSK;
        const float inv = cinv[c];
        #pragma unroll
        for (int it = 0; it < 8; it++) {
            int t4 = it * 64 + l64;
            float4 v = srcc[t4];
            int t = t4 * 4;
            float off = coff[c][t >> 7];
            dst[IDX(t + 0)] = (v.x + off + (float)(t + 1) * shift) * inv;
            dst[IDX(t + 1)] = (v.y + off + (float)(t + 2) * shift) * inv;
            dst[IDX(t + 2)] = (v.z + off + (float)(t + 3) * shift) * inv;
            dst[IDX(t + 3)] = (v.w + off + (float)(t + 4) * shift) * inv;
        }
    }
    __syncthreads();

    // ---- merge-path: 128 threads per problem, 32 merged endpoints each ----
    const int p = tid >> 7;          // problem 0..1
    const int l = tid & 127;         // chunk id
    const int k0 = l * 32;           // merged rank of first element
    const float* A = sm + (p * 2 + 0) * CSK;
    const float* B = sm + (p * 2 + 1) * CSK;

    // diagonal binary search: i = #A among first k0 merged (A-first on ties)
    int lo = (k0 > T_DIM) ? (k0 - T_DIM) : 0;
    int hi = (k0 < T_DIM) ? k0 : T_DIM;
    while (lo < hi) {
        int mid = (lo + hi) >> 1;
        if (A[IDX(mid)] <= B[IDX(k0 - 1 - mid)]) lo = mid + 1;
        else hi = mid;
    }
    int i = lo;
    int j = k0 - lo;

    float prevA = i ? A[IDX(i - 1)] : 0.0f;
    float prevB = j ? B[IDX(j - 1)] : 0.0f;
    float prev = fmaxf(prevA, prevB);
    float aq = (i < T_DIM) ? A[IDX(i)] : FLT_MAX;
    float bq = (j < T_DIM) ? B[IDX(j)] : FLT_MAX;

    float acc = 0.0f;

    if ((tid & 64) == 0) {
        // LEAN: ranks k0..k0+31 all <= 2047 -> no clamps, no bounds checks.
        float fd = (float)(i - j);
        #pragma unroll 8
        for (int s = 0; s < 32; s++) {
            bool takeA = (aq <= bq);
            float q = takeA ? aq : bq;
            acc += (q - prev) * (fd * fd);
            prev = q;
            fd += takeA ? 1.0f : -1.0f;
            if (takeA) { i++; aq = A[IDX(i)]; }
            else       { j++; bq = B[IDX(j)]; }
        }
    } else {
        // CLAMPED: ranks >= 2048 can exhaust one array.
        #pragma unroll 8
        for (int s = 0; s < 32; s++) {
            bool takeA = (aq <= bq);
            float q = takeA ? aq : bq;
            int ic = (i < 2047) ? i : 2047;
            int jc = (j < 2047) ? j : 2047;
            float diff = (float)(ic - jc);
            acc += (q - prev) * (diff * diff);
            prev = q;
            if (takeA) { i++; aq = (i < T_DIM) ? A[IDX(i)] : FLT_MAX; }
            else       { j++; bq = (j < T_DIM) ? B[IDX(j)] : FLT_MAX; }
        }
    }
    acc *= (1.0f / 2048.0f) * (1.0f / 2048.0f);

    // block reduce -> single atomicAdd into out[b]
    for (int o = 16; o; o >>= 1) acc += __shfl_xor_sync(0xffffffffu, acc, o);
    const int wid = tid >> 5;
    if ((tid & 31) == 0) warr[wid] = acc;
    __syncthreads();
    if (tid == 0) {
        float s = 0.0f;
        #pragma unroll
        for (int i2 = 0; i2 < 8; i2++) s += warr[i2];
        atomicAdd(&out[bs >> 3], s);
    }
}

extern "C" void kernel_launch(void* const* d_in, const int* in_sizes, int n_in,
                              void* d_out, int out_size) {
    const float* x = (const float*)d_in[0];
    const float* y = (const float*)d_in[1];
    float* out = (float*)d_out;

    cdf_kernel<<<2 * BS_DIM * 16, 256>>>(x, y, out);
    w2_kernel<<<BS_DIM * (R_DIM / 2), 256>>>(out);
}

// round 7
// speedup vs baseline: 3.2291x; 1.0812x over previous
#include <cuda_runtime.h>
#include <cfloat>

#define T_DIM 2048
#define R_DIM 256
#define BS_DIM 32
#define IDX(t) ((t) + ((t) >> 5))   // smem skew: 1 pad float per 32
#define CSK 2112                    // skewed column size: 2048 + 64

// 128 MB transposed CDF scratch: [array][bs][r][t]
__device__ float g_cdf[2][BS_DIM][R_DIM][T_DIM];
// per-segment totals (segments of 128 t): [array][bs][r][seg16]
__device__ float g_segtot[2][BS_DIM][R_DIM][16];
// per-block minima from cdf_kernel (1024 blocks)
__device__ float g_blockmin[1024];

// ---------------- Kernel A: transpose + segment cumsum + per-block min ----------------
// grid 1024: [array(2)][bs(32)][rtile(8)][thalf(2)], 256 threads.
__global__ void __launch_bounds__(256) cdf_kernel(const float* __restrict__ x,
                                                  const float* __restrict__ y,
                                                  float* __restrict__ out) {
    __shared__ float tile[8][32][33];
    __shared__ float wmin[8];

    const int bid = blockIdx.x;
    const int a    = bid >> 9;
    const int rem  = bid & 511;
    const int bs   = rem >> 4;
    const int rem2 = rem & 15;
    const int r0   = (rem2 >> 1) * 32;
    const int tb   = (rem2 & 1) * 1024;

    if (bid == 0 && threadIdx.x < 4) out[threadIdx.x] = 0.0f;

    const int lane = threadIdx.x & 31;   // r'
    const int seg  = threadIdx.x >> 5;   // warp id -> 128-t segment

    const float* src = (a ? y : x) + (size_t)bs * T_DIM * R_DIM + r0 + lane;

    float run = 0.0f;
    float mn = FLT_MAX;

    const int row = lane >> 3;   // 0..3
    const int c4  = lane & 7;    // 0..7

    #pragma unroll 1
    for (int ch = 0; ch < 4; ch++) {
        const int t0 = tb + seg * 128 + ch * 32;
        float v[32];
        #pragma unroll
        for (int i = 0; i < 32; i++) v[i] = src[(size_t)(t0 + i) * R_DIM];
        #pragma unroll
        for (int i = 0; i < 32; i++) {
            mn = fminf(mn, v[i]);
            run += v[i];
            tile[seg][lane][i] = run;
        }
        __syncwarp();
        // drain transposed: scalar LDS (conflict-free, pad 33) -> STG.128
        #pragma unroll
        for (int rb = 0; rb < 8; rb++) {
            int rr = rb * 4 + row;
            float4 o;
            o.x = tile[seg][rr][c4 * 4 + 0];
            o.y = tile[seg][rr][c4 * 4 + 1];
            o.z = tile[seg][rr][c4 * 4 + 2];
            o.w = tile[seg][rr][c4 * 4 + 3];
            *(float4*)&g_cdf[a][bs][r0 + rr][t0 + c4 * 4] = o;   // 16B-aligned gmem
        }
        __syncwarp();
    }
    g_segtot[a][bs][r0 + lane][(tb >> 7) + seg] = run;

    // block min reduce -> g_blockmin[bid]
    for (int o = 16; o; o >>= 1) mn = fminf(mn, __shfl_xor_sync(0xffffffffu, mn, o));
    if (lane == 0) wmin[seg] = mn;
    __syncthreads();
    if (threadIdx.x == 0) {
        float m = wmin[0];
        #pragma unroll
        for (int i = 1; i < 8; i++) m = fminf(m, wmin[i]);
        g_blockmin[bid] = m;
    }
}

// ---------------- Kernel B: stage normalized CDFs + merge-path W2 ----------------
// grid 4096: [bs(32)][rpair(128)], 256 threads, 2 problems per block.
__global__ void __launch_bounds__(256) w2_kernel(float* __restrict__ out) {
    __shared__ float sm[4 * CSK + 32];   // +32 pad: final-iteration dead loads
    __shared__ float coffs[4][16];       // pre-scaled: off_seg * inv
    __shared__ float cinv[4];
    __shared__ float csinv[4];           // shift * inv
    __shared__ float redsm[8];
    __shared__ float warr[8];

    const int tid = threadIdx.x;
    const int bs  = blockIdx.x >> 7;
    const int r0  = (blockIdx.x & 127) * 2;

    // ---- global min from g_blockmin (1024 entries, L2-resident) ----
    {
        float m = fminf(fminf(g_blockmin[tid],       g_blockmin[tid + 256]),
                        fminf(g_blockmin[tid + 512], g_blockmin[tid + 768]));
        for (int o = 16; o; o >>= 1) m = fminf(m, __shfl_xor_sync(0xffffffffu, m, o));
        if ((tid & 31) == 0) redsm[tid >> 5] = m;
    }
    __syncthreads();
    float mnv = redsm[0];
    #pragma unroll
    for (int i = 1; i < 8; i++) mnv = fminf(mnv, redsm[i]);
    const float shift = (mnv < 0.0f) ? (-1.1f * mnv) : 0.0f;

    // per-column segment-offset prefix + normalization (pre-scaled by inv)
    if (tid < 4) {
        int c = tid, aa = c & 1, pp = c >> 1;
        const float* st = g_segtot[aa][bs][r0 + pp];
        float pref[16];
        float runp = 0.0f;
        #pragma unroll
        for (int s = 0; s < 16; s++) { pref[s] = runp; runp += st[s]; }
        float inv = 1.0f / (runp + 2048.0f * shift);
        cinv[c] = inv;
        csinv[c] = shift * inv;
        #pragma unroll
        for (int s = 0; s < 16; s++) coffs[c][s] = pref[s] * inv;
    }
    __syncthreads();

    // stage: coalesced float4 global loads, 2-FFMA transform, scalar skewed smem stores
    {
        const int c = tid >> 6;
        const int l64 = tid & 63;
        const int aa = c & 1, pp = c >> 1;
        const float4* srcc = (const float4*)&g_cdf[aa][bs][r0 + pp][0];
        float* dst = sm + c * CSK;
        const float inv = cinv[c];
        const float si  = csinv[c];
        const float si2 = si + si;
        float tf = (float)(l64 * 4);     // float t counter, exact
        #pragma unroll
        for (int it = 0; it < 8; it++) {
            int t4 = it * 64 + l64;
            float4 v = srcc[t4];
            int t = t4 * 4;
            // base = off*inv + (t+1)*shift*inv
            float base = fmaf(tf + 1.0f, si, coffs[c][t >> 7]);
            dst[IDX(t + 0)] = fmaf(v.x, inv, base);
            dst[IDX(t + 1)] = fmaf(v.y, inv, base + si);
            dst[IDX(t + 2)] = fmaf(v.z, inv, base + si2);
            dst[IDX(t + 3)] = fmaf(v.w, inv, base + si2 + si);
            tf += 256.0f;
        }
    }
    __syncthreads();

    // ---- merge-path: 128 threads per problem, 32 merged endpoints each ----
    const int p = tid >> 7;          // problem 0..1
    const int l = tid & 127;         // chunk id
    const int k0 = l * 32;           // merged rank of first element
    const float* A = sm + (p * 2 + 0) * CSK;
    const float* B = sm + (p * 2 + 1) * CSK;

    // diagonal binary search: i = #A among first k0 merged (A-first on ties)
    int lo = (k0 > T_DIM) ? (k0 - T_DIM) : 0;
    int hi = (k0 < T_DIM) ? k0 : T_DIM;
    while (lo < hi) {
        int mid = (lo + hi) >> 1;
        if (A[IDX(mid)] <= B[IDX(k0 - 1 - mid)]) lo = mid + 1;
        else hi = mid;
    }
    int i = lo;
    int j = k0 - lo;

    float prevA = i ? A[IDX(i - 1)] : 0.0f;
    float prevB = j ? B[IDX(j - 1)] : 0.0f;
    float prev = fmaxf(prevA, prevB);
    float aq = (i < T_DIM) ? A[IDX(i)] : FLT_MAX;
    float bq = (j < T_DIM) ? B[IDX(j)] : FLT_MAX;

    float acc = 0.0f;

    if ((tid & 64) == 0) {
        // LEAN: ranks k0..k0+31 all <= 2047 -> no clamps, no bounds checks.
        float fd = (float)(i - j);
        #pragma unroll 8
        for (int s = 0; s < 32; s++) {
            bool takeA = (aq <= bq);
            float q = fminf(aq, bq);
            acc += (q - prev) * (fd * fd);
            prev = q;
            fd += takeA ? 1.0f : -1.0f;
            if (takeA) { i++; aq = A[IDX(i)]; }
            else       { j++; bq = B[IDX(j)]; }
        }
    } else {
        // CLAMPED: ranks >= 2048 can exhaust one array.
        #pragma unroll 8
        for (int s = 0; s < 32; s++) {
            bool takeA = (aq <= bq);
            float q = fminf(aq, bq);
            int ic = (i < 2047) ? i : 2047;
            int jc = (j < 2047) ? j : 2047;
            float diff = (float)(ic - jc);
            acc += (q - prev) * (diff * diff);
            prev = q;
            if (takeA) { i++; aq = (i < T_DIM) ? A[IDX(i)] : FLT_MAX; }
            else       { j++; bq = (j < T_DIM) ? B[IDX(j)] : FLT_MAX; }
        }
    }
    acc *= (1.0f / 2048.0f) * (1.0f / 2048.0f);

    // block reduce -> single atomicAdd into out[b]
    for (int o = 16; o; o >>= 1) acc += __shfl_xor_sync(0xffffffffu, acc, o);
    const int wid = tid >> 5;
    if ((tid & 31) == 0) warr[wid] = acc;
    __syncthreads();
    if (tid == 0) {
        float s = 0.0f;
        #pragma unroll
        for (int i2 = 0; i2 < 8; i2++) s += warr[i2];
        atomicAdd(&out[bs >> 3], s);
    }
}

extern "C" void kernel_launch(void* const* d_in, const int* in_sizes, int n_in,
                              void* d_out, int out_size) {
    const float* x = (const float*)d_in[0];
    const float* y = (const float*)d_in[1];
    float* out = (float*)d_out;

    cdf_kernel<<<2 * BS_DIM * 16, 256>>>(x, y, out);
    w2_kernel<<<BS_DIM * (R_DIM / 2), 256>>>(out);
}